// round 13
// baseline (speedup 1.0000x reference)
#include <cuda_runtime.h>
#include <cuda_fp16.h>

#define N_IMGS 2
#define C_CH   256
#define HW_DIM 64
#define HWPIX  (HW_DIM * HW_DIM)      // 4096
#define NPIX   (N_IMGS * HWPIX)       // 8192
#define S_STEPS 64
#define EPSV 1e-3f

// ---------------- scratch (device globals: no allocation allowed) ----------
__device__ float g_F[N_IMGS][9];
__device__ uint4 g_feat2h[(size_t)N_IMGS * HWPIX * C_CH / 8];   // 4 MB, (N,HW,C) half

__device__ __forceinline__ double det3cols(const double c0[3], const double c1[3], const double c2[3]) {
    return c0[0]*(c1[1]*c2[2]-c1[2]*c2[1])
         - c0[1]*(c1[0]*c2[2]-c1[2]*c2[0])
         + c0[2]*(c1[0]*c2[1]-c1[1]*c2[0]);
}

// ---------------- fused prep: block 0 computes F (warp-parallel fp64),
// ---------------- blocks 1..2048 transpose+convert feat2 to (N,HW,C) half --
__global__ __launch_bounds__(256) void prep_kernel(const float* __restrict__ feat2,
                                                   const float* __restrict__ P1g,
                                                   const float* __restrict__ P2g) {
    __shared__ float tile[32][33];
    __shared__ double s_v[N_IMGS][4];
    __shared__ double s_e2[N_IMGS][3];
    __shared__ double s_G[N_IMGS][9];
    __shared__ double s_Gi[N_IMGS][9];
    __shared__ double s_pinv[N_IMGS][12];
    __shared__ double s_B[N_IMGS][9];
    __shared__ double s_rn[N_IMGS], s_rd[N_IMGS];

    if (blockIdx.x == 0) {
        if (threadIdx.y != 0) return;
        int lane = threadIdx.x;
        int n = lane >> 4;
        int r = lane & 15;
        double p1[3][4], p2[3][4];
        #pragma unroll
        for (int i = 0; i < 3; i++)
            #pragma unroll
            for (int j = 0; j < 4; j++) {
                p1[i][j] = (double)P1g[n*12 + i*4 + j];
                p2[i][j] = (double)P2g[n*12 + i*4 + j];
            }
        if (r < 4) {
            double ca[3], cb[3], cc[3];
            int ja = (r == 0) ? 1 : 0;
            int jb = (r <= 1) ? 2 : 1;
            int jc = (r == 3) ? 2 : 3;
            #pragma unroll
            for (int i = 0; i < 3; i++) { ca[i]=p1[i][ja]; cb[i]=p1[i][jb]; cc[i]=p1[i][jc]; }
            double m = det3cols(ca, cb, cc);
            s_v[n][r] = (r & 1) ? -m : m;
        } else if (r < 13) {
            int idx = r - 4;
            int i = idx / 3, k = idx % 3;
            double s = 0.0;
            #pragma unroll
            for (int j = 0; j < 4; j++) s += p1[i][j]*p1[k][j];
            s_G[n][idx] = s;
        }
        __syncwarp();
        if (r == 0) {
            double n2 = s_v[n][0]*s_v[n][0] + s_v[n][1]*s_v[n][1]
                      + s_v[n][2]*s_v[n][2] + s_v[n][3]*s_v[n][3];
            s_rn[n] = 1.0 / sqrt(n2);
        } else if (r == 1) {
            const double* G = s_G[n];
            double detG = G[0]*(G[4]*G[8]-G[5]*G[7])
                        - G[1]*(G[3]*G[8]-G[5]*G[6])
                        + G[2]*(G[3]*G[7]-G[4]*G[6]);
            s_rd[n] = 1.0 / detG;
        }
        __syncwarp();
        if (r < 3) {
            double s = 0.0;
            #pragma unroll
            for (int j = 0; j < 4; j++) s += p2[r][j]*s_v[n][j];
            s_e2[n][r] = s * s_rn[n];
        } else if (r < 12) {
            int idx = r - 3;
            int i = idx / 3, j = idx % 3;
            const double* G = s_G[n];
            int r1 = (j == 0) ? 1 : 0, r2 = (j == 2) ? 1 : 2;
            int c1 = (i == 0) ? 1 : 0, c2 = (i == 2) ? 1 : 2;
            double m = G[r1*3+c1]*G[r2*3+c2] - G[r1*3+c2]*G[r2*3+c1];
            if ((i + j) & 1) m = -m;
            s_Gi[n][idx] = m * s_rd[n];
        }
        __syncwarp();
        if (r < 12) {
            int m_ = r / 3, j = r % 3;
            double s = 0.0;
            #pragma unroll
            for (int k = 0; k < 3; k++) s += p1[k][m_]*s_Gi[n][k*3+j];
            s_pinv[n][r] = s;
        }
        __syncwarp();
        if (r < 9) {
            int i = r / 3, j = r % 3;
            double s = 0.0;
            #pragma unroll
            for (int m_ = 0; m_ < 4; m_++) s += p2[i][m_]*s_pinv[n][m_*3+j];
            s_B[n][r] = s;
        }
        __syncwarp();
        if (r < 9) {
            int i = r / 3, j = r % 3;
            const double* e2 = s_e2[n];
            const double* B  = s_B[n];
            double F;
            if      (i == 0) F = -e2[2]*B[3+j] + e2[1]*B[6+j];
            else if (i == 1) F =  e2[2]*B[j]   - e2[0]*B[6+j];
            else             F = -e2[1]*B[j]   + e2[0]*B[3+j];
            g_F[n][r] = (float)F;
        }
        return;
    }

    // ---- transpose+convert path, float4 loads (8 threads per 32-pixel row) --
    int b  = blockIdx.x - 1;
    int n  = b >> 10;
    int ct = ((b >> 7) & 7) * 32;
    int pt = (b & 127) * 32;
    int tx = threadIdx.x, ty = threadIdx.y;
    const float* src = feat2 + (size_t)n * C_CH * HWPIX;
    {
        int tid = ty * 32 + tx;             // 0..255
        int ch  = tid >> 3;                 // 0..31 channel within tile
        int q4  = (tid & 7) * 4;            // 0,4,..28 pixel quad
        float4 v = *reinterpret_cast<const float4*>(src + (size_t)(ct + ch) * HWPIX + pt + q4);
        tile[ch][q4 + 0] = v.x;
        tile[ch][q4 + 1] = v.y;
        tile[ch][q4 + 2] = v.z;
        tile[ch][q4 + 3] = v.w;
    }
    __syncthreads();
    __half* dst = (__half*)g_feat2h + (size_t)n * HWPIX * C_CH;
    int tid = ty * 32 + tx;
    int c2  = tid & 15;
    int pr  = tid >> 4;
    #pragma unroll
    for (int k = 0; k < 2; k++) {
        int row = pr + 16*k;
        __half2 v = __floats2half2_rn(tile[2*c2][row], tile[2*c2+1][row]);
        ((__half2*)(dst + (size_t)(pt + row) * C_CH + ct))[c2] = v;
    }
}

// predicated v4 load: load only if cond, else keep current register values.
__device__ __forceinline__ void ld_cond(unsigned cond, const char* addr, uint4& v) {
    asm("{\n\t"
        ".reg .pred p;\n\t"
        "setp.ne.u32 p, %4, 0;\n\t"
        "@p ld.global.nc.v4.u32 {%0,%1,%2,%3}, [%5];\n\t"
        "}"
        : "+r"(v.x), "+r"(v.y), "+r"(v.z), "+r"(v.w)
        : "r"(cond), "l"(addr));
}

// FMAs + running max for one sample given corner regs
__device__ __forceinline__ void fma_max(const uint4& wp, const uint4& v00, const uint4& v01,
                                        const uint4& v10, const uint4& v11,
                                        __half2& a0, __half2& a1, __half2& a2, __half2& a3) {
    __half2 w0 = *reinterpret_cast<const __half2*>(&wp.x);
    __half2 w1 = *reinterpret_cast<const __half2*>(&wp.y);
    __half2 w2 = *reinterpret_cast<const __half2*>(&wp.z);
    __half2 w3 = *reinterpret_cast<const __half2*>(&wp.w);
    const __half2* h0 = reinterpret_cast<const __half2*>(&v00);
    const __half2* h1 = reinterpret_cast<const __half2*>(&v01);
    const __half2* h2 = reinterpret_cast<const __half2*>(&v10);
    const __half2* h3 = reinterpret_cast<const __half2*>(&v11);
    __half2 v;
    v = __hmul2(w3, h3[0]); v = __hfma2(w2, h2[0], v); v = __hfma2(w1, h1[0], v); v = __hfma2(w0, h0[0], v);
    a0 = __hmax2(a0, v);
    v = __hmul2(w3, h3[1]); v = __hfma2(w2, h2[1], v); v = __hfma2(w1, h1[1], v); v = __hfma2(w0, h0[1], v);
    a1 = __hmax2(a1, v);
    v = __hmul2(w3, h3[2]); v = __hfma2(w2, h2[2], v); v = __hfma2(w1, h1[2], v); v = __hfma2(w0, h0[2], v);
    a2 = __hmax2(a2, v);
    v = __hmul2(w3, h3[3]); v = __hfma2(w2, h2[3], v); v = __hfma2(w1, h1[3], v); v = __hfma2(w0, h0[3], v);
    a3 = __hmax2(a3, v);
}

// ---------------- fused locs + sampling + max-over-S kernel -----------------
// 4 warps per pixel (16 samples each), 8 warps/block -> 2 pixels/block,
// grid = 4096. Corner-register caching per quarter-line.
__global__ __launch_bounds__(256) void sample_kernel(float* __restrict__ out) {
    __shared__ uint4    s_wgt[2][S_STEPS];   // weights, 2KB
    __shared__ unsigned s_oc [2][S_STEPS];   // packed cell offsets, 0.5KB
    __shared__ uint4    s_acc[2][3][32];     // partial accumulators, 3KB
    __shared__ float    s_out[2][C_CH];      // output staging, 2KB
    int lane  = threadIdx.x;              // 0..31
    int wy    = threadIdx.y;              // 0..7
    int pix   = wy >> 2;                  // 0..1 pixel in block
    int quart = wy & 3;                   // 0..3 quarter of the line
    int qbase = quart * 16;
    int gp    = blockIdx.x * 2 + pix;
    int n     = gp >> 12;
    int p     = gp & 4095;
    const char* fbB = (const char*)g_feat2h + (size_t)(n * HWPIX) * (C_CH * 2) + lane * 16;

    // ---- phase A: epipolar line + this warp's 16 sample weights/offsets ----
    bool pixValid;
    {
        float hf = (float)(p >> 6);
        float wf = (float)(p & 63);
        const float* F = g_F[n];
        float a = F[0]*wf + F[1]*hf + F[2];
        float b = F[3]*wf + F[4]*hf + F[5];
        float c = F[6]*wf + F[7]*hf + F[8];
        float sb = (b > 0.f) ? 1.f : ((b < 0.f) ? -1.f : 0.f);
        float sa = (a > 0.f) ? 1.f : ((a < 0.f) ? -1.f : 0.f);
        float db = sb * fmaxf(fabsf(b), EPSV);
        float da = sa * fmaxf(fabsf(a), EPSV);
        const float xmax = 63.f, ymax = 63.f;
        float by1 = -c / db;
        float by2 = -(xmax*a + c) / db;
        float bx0 = -c / da;
        float bx3 = -(ymax*b + c) / da;
        float px[4] = {bx0, 0.f, xmax, bx3};
        float py[4] = {0.f, by1, by2, ymax};
        bool m0 = (bx0 >= EPSV) && (bx0 <  xmax - EPSV);
        bool m1 = (by1 >  EPSV) && (by1 <= ymax - EPSV);
        bool m2 = (by2 >= EPSV) && (by2 <  ymax - EPSV);
        bool m3 = (bx3 >  EPSV) && (bx3 <= xmax - EPSV);
        int nint = (int)m0 + (int)m1 + (int)m2 + (int)m3;
        bool valid2 = nint >= 2;
        pixValid = valid2;
        if (valid2 && lane < 16) {
            bool mm[4] = {m0, m1, m2, m3};
            int i0 = -1, i1 = -1;
            #pragma unroll
            for (int i = 0; i < 4; i++) {
                if (mm[i]) { if (i0 < 0) i0 = i; else if (i1 < 0) i1 = i; }
            }
            float sx = px[i0], sy = py[i0];
            float vx = px[i1]-px[i0], vy = py[i1]-py[i0];

            int s = qbase + lane;
            float t  = (float)s / 63.0f;
            float lx = sx + vx * t;
            float ly = sy + vy * t;
            float gx = lx / 63.0f * 2.0f - 1.0f;
            float gy = ly / 63.0f * 2.0f - 1.0f;
            float x  = (gx + 1.0f) * 32.0f - 0.5f;
            float y  = (gy + 1.0f) * 32.0f - 0.5f;
            float x0 = floorf(x), y0 = floorf(y);
            float wx1 = x - x0, wy1 = y - y0;
            bool vx0 = (x0        >= 0.f) && (x0        < 64.f);
            bool vx1 = (x0 + 1.f  >= 0.f) && (x0 + 1.f  < 64.f);
            bool vy0 = (y0        >= 0.f) && (y0        < 64.f);
            bool vy1 = (y0 + 1.f  >= 0.f) && (y0 + 1.f  < 64.f);
            float w0 = (vx0 && vy0) ? (1.f - wx1) * (1.f - wy1) : 0.f;
            float w1 = (vx1 && vy0) ? wx1 * (1.f - wy1)         : 0.f;
            float w2 = (vx0 && vy1) ? (1.f - wx1) * wy1         : 0.f;
            float w3 = (vx1 && vy1) ? wx1 * wy1                 : 0.f;
            unsigned u0 = (unsigned)__half_as_ushort(__float2half_rn(w0)) * 0x10001u;
            unsigned u1 = (unsigned)__half_as_ushort(__float2half_rn(w1)) * 0x10001u;
            unsigned u2 = (unsigned)__half_as_ushort(__float2half_rn(w2)) * 0x10001u;
            unsigned u3 = (unsigned)__half_as_ushort(__float2half_rn(w3)) * 0x10001u;
            int cx0 = (int)fminf(fmaxf(x0,       0.f), 63.f);
            int cx1 = (int)fminf(fmaxf(x0 + 1.f, 0.f), 63.f);
            int cy0 = (int)fminf(fmaxf(y0,       0.f), 63.f);
            int cy1 = (int)fminf(fmaxf(y0 + 1.f, 0.f), 63.f);
            unsigned o00 = (unsigned)((cy0*64 + cx0) * 512);
            unsigned oc  = o00 | (unsigned)(cx1 != cx0) | ((unsigned)(cy1 != cy0) << 1);
            s_wgt[pix][s] = make_uint4(u0, u1, u2, u3);
            s_oc [pix][s] = oc;
        }
    }
    __syncwarp();

    __half2 a0, a1, a2, a3;
    if (pixValid) {
        // ---- phase B: 16-iteration loop with corner-register caching ----
        __half2 X0 = __float2half2_rn(-65504.f);
        __half2 X1 = X0, X2 = X0, X3 = X0;
        uint4 v00={0,0,0,0}, v01={0,0,0,0}, v10={0,0,0,0}, v11={0,0,0,0};
        unsigned prev = 0xFFFFFFFFu;
        #pragma unroll 4
        for (int i = 0; i < 16; i++) {
            int s = qbase + i;
            uint4    wp = s_wgt[pix][s];
            unsigned oc = s_oc [pix][s];
            unsigned nl = (oc != prev); prev = oc;
            unsigned o00 = oc & ~3u;
            unsigned dxo = (oc & 1u) << 9;
            unsigned dyo = (oc & 2u) << 14;
            const char* p0 = fbB + o00;
            ld_cond(nl, p0,             v00);
            ld_cond(nl, p0 + dxo,       v01);
            ld_cond(nl, p0 + dyo,       v10);
            ld_cond(nl, p0 + dxo + dyo, v11);
            fma_max(wp, v00, v01, v10, v11, X0, X1, X2, X3);
        }
        a0 = X0; a1 = X1; a2 = X2; a3 = X3;
    } else {
        a0 = __float2half2_rn(0.0f);
        a1 = a0; a2 = a0; a3 = a0;
    }

    // ---- merge the four quarter-line accumulators per pixel ----
    __syncthreads();                      // all warps done reading s_wgt/s_oc
    if (quart) {
        uint4 pk;
        pk.x = *reinterpret_cast<unsigned*>(&a0);
        pk.y = *reinterpret_cast<unsigned*>(&a1);
        pk.z = *reinterpret_cast<unsigned*>(&a2);
        pk.w = *reinterpret_cast<unsigned*>(&a3);
        s_acc[pix][quart - 1][lane] = pk;
    }
    __syncthreads();
    if (quart == 0) {
        #pragma unroll
        for (int q = 0; q < 3; q++) {
            uint4 pk = s_acc[pix][q][lane];
            a0 = __hmax2(a0, *reinterpret_cast<__half2*>(&pk.x));
            a1 = __hmax2(a1, *reinterpret_cast<__half2*>(&pk.y));
            a2 = __hmax2(a2, *reinterpret_cast<__half2*>(&pk.z));
            a3 = __hmax2(a3, *reinterpret_cast<__half2*>(&pk.w));
        }
        float* row = &s_out[pix][0];
        float2 t;
        t = __half22float2(a0); row[lane*8 + 0] = t.x; row[lane*8 + 1] = t.y;
        t = __half22float2(a1); row[lane*8 + 2] = t.x; row[lane*8 + 3] = t.y;
        t = __half22float2(a2); row[lane*8 + 4] = t.x; row[lane*8 + 5] = t.y;
        t = __half22float2(a3); row[lane*8 + 6] = t.x; row[lane*8 + 7] = t.y;
    }
    __syncthreads();

    // ---- coalesced store: thread = channel, 2 pixels -> 1x STG.64 ----
    {
        int c   = wy * 32 + lane;          // 0..255
        int gpb = blockIdx.x * 2;
        int nB  = gpb >> 12;
        int pB  = gpb & 4095;
        float2 o2 = make_float2(s_out[0][c], s_out[1][c]);
        size_t base = ((size_t)(nB * C_CH + c)) * HWPIX + pB;
        *reinterpret_cast<float2*>(out + base) = o2;
    }
}

// ---------------- launch ------------------------------------------------------
extern "C" void kernel_launch(void* const* d_in, const int* in_sizes, int n_in,
                              void* d_out, int out_size) {
    (void)in_sizes; (void)n_in; (void)out_size;
    const float* feat2 = (const float*)d_in[1];
    const float* P1    = (const float*)d_in[2];
    const float* P2    = (const float*)d_in[3];

    prep_kernel<<<2049, dim3(32, 8)>>>(feat2, P1, P2);
    sample_kernel<<<NPIX / 2, dim3(32, 8)>>>((float*)d_out);
}

// round 14
// speedup vs baseline: 1.0936x; 1.0936x over previous
#include <cuda_runtime.h>
#include <cuda_fp16.h>

#define N_IMGS 2
#define C_CH   256
#define HW_DIM 64
#define HWPIX  (HW_DIM * HW_DIM)      // 4096
#define NPIX   (N_IMGS * HWPIX)       // 8192
#define S_STEPS 64
#define EPSV 1e-3f

// ---------------- scratch (device globals: no allocation allowed) ----------
__device__ float g_F[N_IMGS][9];
__device__ uint4 g_feat2h[(size_t)N_IMGS * HWPIX * C_CH / 8];   // 4 MB, (N,HW,C) half

__device__ __forceinline__ double det3cols(const double c0[3], const double c1[3], const double c2[3]) {
    return c0[0]*(c1[1]*c2[2]-c1[2]*c2[1])
         - c0[1]*(c1[0]*c2[2]-c1[2]*c2[0])
         + c0[2]*(c1[0]*c2[1]-c1[1]*c2[0]);
}

// ---------------- fused prep: block 0 computes F (warp-parallel fp64),
// ---------------- blocks 1..2048 transpose+convert feat2 to (N,HW,C) half --
__global__ __launch_bounds__(256) void prep_kernel(const float* __restrict__ feat2,
                                                   const float* __restrict__ P1g,
                                                   const float* __restrict__ P2g) {
    __shared__ float tile[32][33];
    __shared__ double s_v[N_IMGS][4];
    __shared__ double s_e2[N_IMGS][3];
    __shared__ double s_G[N_IMGS][9];
    __shared__ double s_Gi[N_IMGS][9];
    __shared__ double s_pinv[N_IMGS][12];
    __shared__ double s_B[N_IMGS][9];
    __shared__ double s_rn[N_IMGS], s_rd[N_IMGS];

    if (blockIdx.x == 0) {
        if (threadIdx.y != 0) return;
        int lane = threadIdx.x;
        int n = lane >> 4;
        int r = lane & 15;
        double p1[3][4], p2[3][4];
        #pragma unroll
        for (int i = 0; i < 3; i++)
            #pragma unroll
            for (int j = 0; j < 4; j++) {
                p1[i][j] = (double)P1g[n*12 + i*4 + j];
                p2[i][j] = (double)P2g[n*12 + i*4 + j];
            }
        if (r < 4) {
            double ca[3], cb[3], cc[3];
            int ja = (r == 0) ? 1 : 0;
            int jb = (r <= 1) ? 2 : 1;
            int jc = (r == 3) ? 2 : 3;
            #pragma unroll
            for (int i = 0; i < 3; i++) { ca[i]=p1[i][ja]; cb[i]=p1[i][jb]; cc[i]=p1[i][jc]; }
            double m = det3cols(ca, cb, cc);
            s_v[n][r] = (r & 1) ? -m : m;
        } else if (r < 13) {
            int idx = r - 4;
            int i = idx / 3, k = idx % 3;
            double s = 0.0;
            #pragma unroll
            for (int j = 0; j < 4; j++) s += p1[i][j]*p1[k][j];
            s_G[n][idx] = s;
        }
        __syncwarp();
        if (r == 0) {
            double n2 = s_v[n][0]*s_v[n][0] + s_v[n][1]*s_v[n][1]
                      + s_v[n][2]*s_v[n][2] + s_v[n][3]*s_v[n][3];
            s_rn[n] = 1.0 / sqrt(n2);
        } else if (r == 1) {
            const double* G = s_G[n];
            double detG = G[0]*(G[4]*G[8]-G[5]*G[7])
                        - G[1]*(G[3]*G[8]-G[5]*G[6])
                        + G[2]*(G[3]*G[7]-G[4]*G[6]);
            s_rd[n] = 1.0 / detG;
        }
        __syncwarp();
        if (r < 3) {
            double s = 0.0;
            #pragma unroll
            for (int j = 0; j < 4; j++) s += p2[r][j]*s_v[n][j];
            s_e2[n][r] = s * s_rn[n];
        } else if (r < 12) {
            int idx = r - 3;
            int i = idx / 3, j = idx % 3;
            const double* G = s_G[n];
            int r1 = (j == 0) ? 1 : 0, r2 = (j == 2) ? 1 : 2;
            int c1 = (i == 0) ? 1 : 0, c2 = (i == 2) ? 1 : 2;
            double m = G[r1*3+c1]*G[r2*3+c2] - G[r1*3+c2]*G[r2*3+c1];
            if ((i + j) & 1) m = -m;
            s_Gi[n][idx] = m * s_rd[n];
        }
        __syncwarp();
        if (r < 12) {
            int m_ = r / 3, j = r % 3;
            double s = 0.0;
            #pragma unroll
            for (int k = 0; k < 3; k++) s += p1[k][m_]*s_Gi[n][k*3+j];
            s_pinv[n][r] = s;
        }
        __syncwarp();
        if (r < 9) {
            int i = r / 3, j = r % 3;
            double s = 0.0;
            #pragma unroll
            for (int m_ = 0; m_ < 4; m_++) s += p2[i][m_]*s_pinv[n][m_*3+j];
            s_B[n][r] = s;
        }
        __syncwarp();
        if (r < 9) {
            int i = r / 3, j = r % 3;
            const double* e2 = s_e2[n];
            const double* B  = s_B[n];
            double F;
            if      (i == 0) F = -e2[2]*B[3+j] + e2[1]*B[6+j];
            else if (i == 1) F =  e2[2]*B[j]   - e2[0]*B[6+j];
            else             F = -e2[1]*B[j]   + e2[0]*B[3+j];
            g_F[n][r] = (float)F;
        }
        return;
    }

    // ---- transpose+convert path, float4 loads (8 threads per 32-pixel row) --
    int b  = blockIdx.x - 1;
    int n  = b >> 10;
    int ct = ((b >> 7) & 7) * 32;
    int pt = (b & 127) * 32;
    int tx = threadIdx.x, ty = threadIdx.y;
    const float* src = feat2 + (size_t)n * C_CH * HWPIX;
    {
        int tid = ty * 32 + tx;             // 0..255
        int ch  = tid >> 3;                 // 0..31 channel within tile
        int q4  = (tid & 7) * 4;            // 0,4,..28 pixel quad
        float4 v = *reinterpret_cast<const float4*>(src + (size_t)(ct + ch) * HWPIX + pt + q4);
        tile[ch][q4 + 0] = v.x;
        tile[ch][q4 + 1] = v.y;
        tile[ch][q4 + 2] = v.z;
        tile[ch][q4 + 3] = v.w;
    }
    __syncthreads();
    __half* dst = (__half*)g_feat2h + (size_t)n * HWPIX * C_CH;
    int tid = ty * 32 + tx;
    int c2  = tid & 15;
    int pr  = tid >> 4;
    #pragma unroll
    for (int k = 0; k < 2; k++) {
        int row = pr + 16*k;
        __half2 v = __floats2half2_rn(tile[2*c2][row], tile[2*c2+1][row]);
        ((__half2*)(dst + (size_t)(pt + row) * C_CH + ct))[c2] = v;
    }
}

// predicated v4 load: load only if cond, else keep current register values.
__device__ __forceinline__ void ld_cond(unsigned cond, const char* addr, uint4& v) {
    asm("{\n\t"
        ".reg .pred p;\n\t"
        "setp.ne.u32 p, %4, 0;\n\t"
        "@p ld.global.nc.v4.u32 {%0,%1,%2,%3}, [%5];\n\t"
        "}"
        : "+r"(v.x), "+r"(v.y), "+r"(v.z), "+r"(v.w)
        : "r"(cond), "l"(addr));
}

// FMAs + running max for one sample given corner regs
__device__ __forceinline__ void fma_max(const uint4& wp, const uint4& v00, const uint4& v01,
                                        const uint4& v10, const uint4& v11,
                                        __half2& a0, __half2& a1, __half2& a2, __half2& a3) {
    __half2 w0 = *reinterpret_cast<const __half2*>(&wp.x);
    __half2 w1 = *reinterpret_cast<const __half2*>(&wp.y);
    __half2 w2 = *reinterpret_cast<const __half2*>(&wp.z);
    __half2 w3 = *reinterpret_cast<const __half2*>(&wp.w);
    const __half2* h0 = reinterpret_cast<const __half2*>(&v00);
    const __half2* h1 = reinterpret_cast<const __half2*>(&v01);
    const __half2* h2 = reinterpret_cast<const __half2*>(&v10);
    const __half2* h3 = reinterpret_cast<const __half2*>(&v11);
    __half2 v;
    v = __hmul2(w3, h3[0]); v = __hfma2(w2, h2[0], v); v = __hfma2(w1, h1[0], v); v = __hfma2(w0, h0[0], v);
    a0 = __hmax2(a0, v);
    v = __hmul2(w3, h3[1]); v = __hfma2(w2, h2[1], v); v = __hfma2(w1, h1[1], v); v = __hfma2(w0, h0[1], v);
    a1 = __hmax2(a1, v);
    v = __hmul2(w3, h3[2]); v = __hfma2(w2, h2[2], v); v = __hfma2(w1, h1[2], v); v = __hfma2(w0, h0[2], v);
    a2 = __hmax2(a2, v);
    v = __hmul2(w3, h3[3]); v = __hfma2(w2, h2[3], v); v = __hfma2(w1, h1[3], v); v = __hfma2(w0, h0[3], v);
    a3 = __hmax2(a3, v);
}

// ---------------- fused locs + sampling + max-over-S kernel -----------------
// 2 warps per pixel (each handles 32 of the 64 samples), 8 warps/block ->
// 4 pixels/block, grid = 2048. Corner-register caching per half-line.
__global__ __launch_bounds__(256) void sample_kernel(float* __restrict__ out) {
    __shared__ uint4    s_wgt[4][S_STEPS];   // weights, 4KB (reused as acc buffer)
    __shared__ unsigned s_oc [4][S_STEPS];   // packed cell offsets, 1KB
    __shared__ float    s_out[4][C_CH];      // output staging, 4KB
    int lane  = threadIdx.x;              // 0..31
    int wy    = threadIdx.y;              // 0..7
    int pix   = wy >> 1;                  // 0..3 pixel in block
    int shalf = (wy & 1) * 32;            // this warp's sample range
    int gp    = blockIdx.x * 4 + pix;
    int n     = gp >> 12;
    int p     = gp & 4095;
    const char* fbB = (const char*)g_feat2h + (size_t)(n * HWPIX) * (C_CH * 2) + lane * 16;

    // ---- phase A: epipolar line + this warp's 32 sample weights/offsets ----
    bool pixValid;
    {
        float hf = (float)(p >> 6);
        float wf = (float)(p & 63);
        const float* F = g_F[n];
        float a = F[0]*wf + F[1]*hf + F[2];
        float b = F[3]*wf + F[4]*hf + F[5];
        float c = F[6]*wf + F[7]*hf + F[8];
        float sb = (b > 0.f) ? 1.f : ((b < 0.f) ? -1.f : 0.f);
        float sa = (a > 0.f) ? 1.f : ((a < 0.f) ? -1.f : 0.f);
        float db = sb * fmaxf(fabsf(b), EPSV);
        float da = sa * fmaxf(fabsf(a), EPSV);
        const float xmax = 63.f, ymax = 63.f;
        float by1 = -c / db;
        float by2 = -(xmax*a + c) / db;
        float bx0 = -c / da;
        float bx3 = -(ymax*b + c) / da;
        float px[4] = {bx0, 0.f, xmax, bx3};
        float py[4] = {0.f, by1, by2, ymax};
        bool m0 = (bx0 >= EPSV) && (bx0 <  xmax - EPSV);
        bool m1 = (by1 >  EPSV) && (by1 <= ymax - EPSV);
        bool m2 = (by2 >= EPSV) && (by2 <  ymax - EPSV);
        bool m3 = (bx3 >  EPSV) && (bx3 <= xmax - EPSV);
        int nint = (int)m0 + (int)m1 + (int)m2 + (int)m3;
        bool valid2 = nint >= 2;
        pixValid = valid2;
        if (valid2) {
            bool mm[4] = {m0, m1, m2, m3};
            int i0 = -1, i1 = -1;
            #pragma unroll
            for (int i = 0; i < 4; i++) {
                if (mm[i]) { if (i0 < 0) i0 = i; else if (i1 < 0) i1 = i; }
            }
            float sx = px[i0], sy = py[i0];
            float vx = px[i1]-px[i0], vy = py[i1]-py[i0];

            int s = shalf + lane;
            float t  = (float)s / 63.0f;
            float lx = sx + vx * t;
            float ly = sy + vy * t;
            float gx = lx / 63.0f * 2.0f - 1.0f;
            float gy = ly / 63.0f * 2.0f - 1.0f;
            float x  = (gx + 1.0f) * 32.0f - 0.5f;
            float y  = (gy + 1.0f) * 32.0f - 0.5f;
            float x0 = floorf(x), y0 = floorf(y);
            float wx1 = x - x0, wy1 = y - y0;
            bool vx0 = (x0        >= 0.f) && (x0        < 64.f);
            bool vx1 = (x0 + 1.f  >= 0.f) && (x0 + 1.f  < 64.f);
            bool vy0 = (y0        >= 0.f) && (y0        < 64.f);
            bool vy1 = (y0 + 1.f  >= 0.f) && (y0 + 1.f  < 64.f);
            float w0 = (vx0 && vy0) ? (1.f - wx1) * (1.f - wy1) : 0.f;
            float w1 = (vx1 && vy0) ? wx1 * (1.f - wy1)         : 0.f;
            float w2 = (vx0 && vy1) ? (1.f - wx1) * wy1         : 0.f;
            float w3 = (vx1 && vy1) ? wx1 * wy1                 : 0.f;
            unsigned u0 = (unsigned)__half_as_ushort(__float2half_rn(w0)) * 0x10001u;
            unsigned u1 = (unsigned)__half_as_ushort(__float2half_rn(w1)) * 0x10001u;
            unsigned u2 = (unsigned)__half_as_ushort(__float2half_rn(w2)) * 0x10001u;
            unsigned u3 = (unsigned)__half_as_ushort(__float2half_rn(w3)) * 0x10001u;
            int cx0 = (int)fminf(fmaxf(x0,       0.f), 63.f);
            int cx1 = (int)fminf(fmaxf(x0 + 1.f, 0.f), 63.f);
            int cy0 = (int)fminf(fmaxf(y0,       0.f), 63.f);
            int cy1 = (int)fminf(fmaxf(y0 + 1.f, 0.f), 63.f);
            unsigned o00 = (unsigned)((cy0*64 + cx0) * 512);
            unsigned oc  = o00 | (unsigned)(cx1 != cx0) | ((unsigned)(cy1 != cy0) << 1);
            s_wgt[pix][s] = make_uint4(u0, u1, u2, u3);
            s_oc [pix][s] = oc;
        }
    }
    __syncwarp();

    __half2 a0, a1, a2, a3;
    if (pixValid) {
        // ---- phase B: 32-iteration loop with corner-register caching ----
        __half2 X0 = __float2half2_rn(-65504.f);
        __half2 X1 = X0, X2 = X0, X3 = X0;
        uint4 v00={0,0,0,0}, v01={0,0,0,0}, v10={0,0,0,0}, v11={0,0,0,0};
        unsigned prev = 0xFFFFFFFFu;
        #pragma unroll 4
        for (int i = 0; i < 32; i++) {
            int s = shalf + i;
            uint4    wp = s_wgt[pix][s];
            unsigned oc = s_oc [pix][s];
            unsigned nl = (oc != prev); prev = oc;
            unsigned o00 = oc & ~3u;
            unsigned dxo = (oc & 1u) << 9;
            unsigned dyo = (oc & 2u) << 14;
            const char* p0 = fbB + o00;
            ld_cond(nl, p0,             v00);
            ld_cond(nl, p0 + dxo,       v01);
            ld_cond(nl, p0 + dyo,       v10);
            ld_cond(nl, p0 + dxo + dyo, v11);
            fma_max(wp, v00, v01, v10, v11, X0, X1, X2, X3);
        }
        a0 = X0; a1 = X1; a2 = X2; a3 = X3;
    } else {
        a0 = __float2half2_rn(0.0f);
        a1 = a0; a2 = a0; a3 = a0;
    }

    // ---- merge the two half-line accumulators per pixel ----
    __syncthreads();                       // all warps done reading s_wgt/s_oc
    uint4* s_acc = (uint4*)&s_wgt[0][0];   // reuse weight buffer (4 pix x 32 lanes)
    if (wy & 1) {
        uint4 pk;
        pk.x = *reinterpret_cast<unsigned*>(&a0);
        pk.y = *reinterpret_cast<unsigned*>(&a1);
        pk.z = *reinterpret_cast<unsigned*>(&a2);
        pk.w = *reinterpret_cast<unsigned*>(&a3);
        s_acc[pix * 32 + lane] = pk;
    }
    __syncthreads();
    if (!(wy & 1)) {
        uint4 pk = s_acc[pix * 32 + lane];
        a0 = __hmax2(a0, *reinterpret_cast<__half2*>(&pk.x));
        a1 = __hmax2(a1, *reinterpret_cast<__half2*>(&pk.y));
        a2 = __hmax2(a2, *reinterpret_cast<__half2*>(&pk.z));
        a3 = __hmax2(a3, *reinterpret_cast<__half2*>(&pk.w));
        float* row = &s_out[pix][0];
        float2 t;
        t = __half22float2(a0); row[lane*8 + 0] = t.x; row[lane*8 + 1] = t.y;
        t = __half22float2(a1); row[lane*8 + 2] = t.x; row[lane*8 + 3] = t.y;
        t = __half22float2(a2); row[lane*8 + 4] = t.x; row[lane*8 + 5] = t.y;
        t = __half22float2(a3); row[lane*8 + 6] = t.x; row[lane*8 + 7] = t.y;
    }
    __syncthreads();

    // ---- coalesced store: thread = channel, 4 pixels -> 1x STG.128 ----
    {
        int c   = wy * 32 + lane;          // 0..255
        int gpb = blockIdx.x * 4;
        int nB  = gpb >> 12;
        int pB  = gpb & 4095;
        float4 o4 = make_float4(s_out[0][c], s_out[1][c], s_out[2][c], s_out[3][c]);
        size_t base = ((size_t)(nB * C_CH + c)) * HWPIX + pB;
        *reinterpret_cast<float4*>(out + base) = o4;
    }
}

// ---------------- launch ------------------------------------------------------
extern "C" void kernel_launch(void* const* d_in, const int* in_sizes, int n_in,
                              void* d_out, int out_size) {
    (void)in_sizes; (void)n_in; (void)out_size;
    const float* feat2 = (const float*)d_in[1];
    const float* P1    = (const float*)d_in[2];
    const float* P2    = (const float*)d_in[3];

    prep_kernel<<<2049, dim3(32, 8)>>>(feat2, P1, P2);
    sample_kernel<<<NPIX / 4, dim3(32, 8)>>>((float*)d_out);
}

// round 15
// speedup vs baseline: 1.1090x; 1.0141x over previous
#include <cuda_runtime.h>
#include <cuda_fp16.h>

#define N_IMGS 2
#define C_CH   256
#define HW_DIM 64
#define HWPIX  (HW_DIM * HW_DIM)      // 4096
#define NPIX   (N_IMGS * HWPIX)       // 8192
#define S_STEPS 64
#define EPSV 1e-3f

// ---------------- scratch (device globals: no allocation allowed) ----------
__device__ float g_F[N_IMGS][9];
__device__ uint4 g_feat2h[(size_t)N_IMGS * HWPIX * C_CH / 8];   // 4 MB, (N,HW,C) half

__device__ __forceinline__ double det3cols(const double c0[3], const double c1[3], const double c2[3]) {
    return c0[0]*(c1[1]*c2[2]-c1[2]*c2[1])
         - c0[1]*(c1[0]*c2[2]-c1[2]*c2[0])
         + c0[2]*(c1[0]*c2[1]-c1[1]*c2[0]);
}

// ---------------- fused prep: block 0 computes F (warp-parallel fp64),
// ---------------- blocks 1..1024 transpose+convert 2 tiles each -----------
__global__ __launch_bounds__(256) void prep_kernel(const float* __restrict__ feat2,
                                                   const float* __restrict__ P1g,
                                                   const float* __restrict__ P2g) {
    __shared__ float tile[32][33];
    __shared__ double s_v[N_IMGS][4];
    __shared__ double s_e2[N_IMGS][3];
    __shared__ double s_G[N_IMGS][9];
    __shared__ double s_Gi[N_IMGS][9];
    __shared__ double s_pinv[N_IMGS][12];
    __shared__ double s_B[N_IMGS][9];
    __shared__ double s_rn[N_IMGS], s_rd[N_IMGS];

    if (blockIdx.x == 0) {
        if (threadIdx.y != 0) return;
        int lane = threadIdx.x;
        int n = lane >> 4;
        int r = lane & 15;
        double p1[3][4], p2[3][4];
        #pragma unroll
        for (int i = 0; i < 3; i++)
            #pragma unroll
            for (int j = 0; j < 4; j++) {
                p1[i][j] = (double)P1g[n*12 + i*4 + j];
                p2[i][j] = (double)P2g[n*12 + i*4 + j];
            }
        if (r < 4) {
            double ca[3], cb[3], cc[3];
            int ja = (r == 0) ? 1 : 0;
            int jb = (r <= 1) ? 2 : 1;
            int jc = (r == 3) ? 2 : 3;
            #pragma unroll
            for (int i = 0; i < 3; i++) { ca[i]=p1[i][ja]; cb[i]=p1[i][jb]; cc[i]=p1[i][jc]; }
            double m = det3cols(ca, cb, cc);
            s_v[n][r] = (r & 1) ? -m : m;
        } else if (r < 13) {
            int idx = r - 4;
            int i = idx / 3, k = idx % 3;
            double s = 0.0;
            #pragma unroll
            for (int j = 0; j < 4; j++) s += p1[i][j]*p1[k][j];
            s_G[n][idx] = s;
        }
        __syncwarp();
        if (r == 0) {
            double n2 = s_v[n][0]*s_v[n][0] + s_v[n][1]*s_v[n][1]
                      + s_v[n][2]*s_v[n][2] + s_v[n][3]*s_v[n][3];
            s_rn[n] = 1.0 / sqrt(n2);
        } else if (r == 1) {
            const double* G = s_G[n];
            double detG = G[0]*(G[4]*G[8]-G[5]*G[7])
                        - G[1]*(G[3]*G[8]-G[5]*G[6])
                        + G[2]*(G[3]*G[7]-G[4]*G[6]);
            s_rd[n] = 1.0 / detG;
        }
        __syncwarp();
        if (r < 3) {
            double s = 0.0;
            #pragma unroll
            for (int j = 0; j < 4; j++) s += p2[r][j]*s_v[n][j];
            s_e2[n][r] = s * s_rn[n];
        } else if (r < 12) {
            int idx = r - 3;
            int i = idx / 3, j = idx % 3;
            const double* G = s_G[n];
            int r1 = (j == 0) ? 1 : 0, r2 = (j == 2) ? 1 : 2;
            int c1 = (i == 0) ? 1 : 0, c2 = (i == 2) ? 1 : 2;
            double m = G[r1*3+c1]*G[r2*3+c2] - G[r1*3+c2]*G[r2*3+c1];
            if ((i + j) & 1) m = -m;
            s_Gi[n][idx] = m * s_rd[n];
        }
        __syncwarp();
        if (r < 12) {
            int m_ = r / 3, j = r % 3;
            double s = 0.0;
            #pragma unroll
            for (int k = 0; k < 3; k++) s += p1[k][m_]*s_Gi[n][k*3+j];
            s_pinv[n][r] = s;
        }
        __syncwarp();
        if (r < 9) {
            int i = r / 3, j = r % 3;
            double s = 0.0;
            #pragma unroll
            for (int m_ = 0; m_ < 4; m_++) s += p2[i][m_]*s_pinv[n][m_*3+j];
            s_B[n][r] = s;
        }
        __syncwarp();
        if (r < 9) {
            int i = r / 3, j = r % 3;
            const double* e2 = s_e2[n];
            const double* B  = s_B[n];
            double F;
            if      (i == 0) F = -e2[2]*B[3+j] + e2[1]*B[6+j];
            else if (i == 1) F =  e2[2]*B[j]   - e2[0]*B[6+j];
            else             F = -e2[1]*B[j]   + e2[0]*B[3+j];
            g_F[n][r] = (float)F;
        }
        return;
    }

    // ---- transpose+convert path: 2 tiles per block ----
    int tid = threadIdx.y * 32 + threadIdx.x;       // 0..255
    #pragma unroll
    for (int it = 0; it < 2; it++) {
        int b  = (blockIdx.x - 1) * 2 + it;         // 0..2047
        int n  = b >> 10;
        int ct = ((b >> 7) & 7) * 32;
        int pt = (b & 127) * 32;
        const float* src = feat2 + (size_t)n * C_CH * HWPIX;
        // load: 256 threads, each a float4 (8 threads per 32-pixel channel row)
        {
            int ch = tid >> 3;                      // 0..31 channel within tile
            int q4 = (tid & 7) * 4;                 // pixel quad
            float4 v = *reinterpret_cast<const float4*>(src + (size_t)(ct + ch) * HWPIX + pt + q4);
            tile[ch][q4 + 0] = v.x;
            tile[ch][q4 + 1] = v.y;
            tile[ch][q4 + 2] = v.z;
            tile[ch][q4 + 3] = v.w;
        }
        __syncthreads();
        // write: 256 threads, each 4 channels of one pixel row -> STG.64
        {
            __half* dst = (__half*)g_feat2h + (size_t)n * HWPIX * C_CH;
            int row = tid >> 3;                     // 0..31 pixel within tile
            int chq = (tid & 7) * 4;                // 0,4,..28 channel quad
            __half2 v0 = __floats2half2_rn(tile[chq + 0][row], tile[chq + 1][row]);
            __half2 v1 = __floats2half2_rn(tile[chq + 2][row], tile[chq + 3][row]);
            unsigned u0 = *reinterpret_cast<unsigned*>(&v0);
            unsigned u1 = *reinterpret_cast<unsigned*>(&v1);
            uint2 pk = make_uint2(u0, u1);
            *reinterpret_cast<uint2*>(dst + (size_t)(pt + row) * C_CH + ct + chq) = pk;
        }
        __syncthreads();
    }
}

// predicated v4 load: load only if cond, else keep current register values.
__device__ __forceinline__ void ld_cond(unsigned cond, const char* addr, uint4& v) {
    asm("{\n\t"
        ".reg .pred p;\n\t"
        "setp.ne.u32 p, %4, 0;\n\t"
        "@p ld.global.nc.v4.u32 {%0,%1,%2,%3}, [%5];\n\t"
        "}"
        : "+r"(v.x), "+r"(v.y), "+r"(v.z), "+r"(v.w)
        : "r"(cond), "l"(addr));
}

// FMAs + running max for one sample given corner regs
__device__ __forceinline__ void fma_max(const uint4& wp, const uint4& v00, const uint4& v01,
                                        const uint4& v10, const uint4& v11,
                                        __half2& a0, __half2& a1, __half2& a2, __half2& a3) {
    __half2 w0 = *reinterpret_cast<const __half2*>(&wp.x);
    __half2 w1 = *reinterpret_cast<const __half2*>(&wp.y);
    __half2 w2 = *reinterpret_cast<const __half2*>(&wp.z);
    __half2 w3 = *reinterpret_cast<const __half2*>(&wp.w);
    const __half2* h0 = reinterpret_cast<const __half2*>(&v00);
    const __half2* h1 = reinterpret_cast<const __half2*>(&v01);
    const __half2* h2 = reinterpret_cast<const __half2*>(&v10);
    const __half2* h3 = reinterpret_cast<const __half2*>(&v11);
    __half2 v;
    v = __hmul2(w3, h3[0]); v = __hfma2(w2, h2[0], v); v = __hfma2(w1, h1[0], v); v = __hfma2(w0, h0[0], v);
    a0 = __hmax2(a0, v);
    v = __hmul2(w3, h3[1]); v = __hfma2(w2, h2[1], v); v = __hfma2(w1, h1[1], v); v = __hfma2(w0, h0[1], v);
    a1 = __hmax2(a1, v);
    v = __hmul2(w3, h3[2]); v = __hfma2(w2, h2[2], v); v = __hfma2(w1, h1[2], v); v = __hfma2(w0, h0[2], v);
    a2 = __hmax2(a2, v);
    v = __hmul2(w3, h3[3]); v = __hfma2(w2, h2[3], v); v = __hfma2(w1, h1[3], v); v = __hfma2(w0, h0[3], v);
    a3 = __hmax2(a3, v);
}

// ---------------- fused locs + sampling + max-over-S kernel -----------------
// 2 warps per pixel (each handles 32 of the 64 samples), 8 warps/block ->
// 4 pixels/block, grid = 2048. Corner-register caching per half-line.
__global__ __launch_bounds__(256) void sample_kernel(float* __restrict__ out) {
    __shared__ uint4    s_wgt[4][S_STEPS];   // weights, 4KB (reused as acc buffer)
    __shared__ unsigned s_oc [4][S_STEPS];   // packed cell offsets, 1KB
    __shared__ float    s_out[4][C_CH];      // output staging, 4KB
    int lane  = threadIdx.x;              // 0..31
    int wy    = threadIdx.y;              // 0..7
    int pix   = wy >> 1;                  // 0..3 pixel in block
    int shalf = (wy & 1) * 32;            // this warp's sample range
    int gp    = blockIdx.x * 4 + pix;
    int n     = gp >> 12;
    int p     = gp & 4095;
    const char* fbB = (const char*)g_feat2h + (size_t)(n * HWPIX) * (C_CH * 2) + lane * 16;

    // ---- phase A: epipolar line + this warp's 32 sample weights/offsets ----
    bool pixValid;
    {
        float hf = (float)(p >> 6);
        float wf = (float)(p & 63);
        const float* F = g_F[n];
        float a = F[0]*wf + F[1]*hf + F[2];
        float b = F[3]*wf + F[4]*hf + F[5];
        float c = F[6]*wf + F[7]*hf + F[8];
        float sb = (b > 0.f) ? 1.f : ((b < 0.f) ? -1.f : 0.f);
        float sa = (a > 0.f) ? 1.f : ((a < 0.f) ? -1.f : 0.f);
        float db = sb * fmaxf(fabsf(b), EPSV);
        float da = sa * fmaxf(fabsf(a), EPSV);
        const float xmax = 63.f, ymax = 63.f;
        float by1 = -c / db;
        float by2 = -(xmax*a + c) / db;
        float bx0 = -c / da;
        float bx3 = -(ymax*b + c) / da;
        float px[4] = {bx0, 0.f, xmax, bx3};
        float py[4] = {0.f, by1, by2, ymax};
        bool m0 = (bx0 >= EPSV) && (bx0 <  xmax - EPSV);
        bool m1 = (by1 >  EPSV) && (by1 <= ymax - EPSV);
        bool m2 = (by2 >= EPSV) && (by2 <  ymax - EPSV);
        bool m3 = (bx3 >  EPSV) && (bx3 <= xmax - EPSV);
        int nint = (int)m0 + (int)m1 + (int)m2 + (int)m3;
        bool valid2 = nint >= 2;
        pixValid = valid2;
        if (valid2) {
            bool mm[4] = {m0, m1, m2, m3};
            int i0 = -1, i1 = -1;
            #pragma unroll
            for (int i = 0; i < 4; i++) {
                if (mm[i]) { if (i0 < 0) i0 = i; else if (i1 < 0) i1 = i; }
            }
            float sx = px[i0], sy = py[i0];
            float vx = px[i1]-px[i0], vy = py[i1]-py[i0];

            int s = shalf + lane;
            float t  = (float)s / 63.0f;
            float lx = sx + vx * t;
            float ly = sy + vy * t;
            float gx = lx / 63.0f * 2.0f - 1.0f;
            float gy = ly / 63.0f * 2.0f - 1.0f;
            float x  = (gx + 1.0f) * 32.0f - 0.5f;
            float y  = (gy + 1.0f) * 32.0f - 0.5f;
            float x0 = floorf(x), y0 = floorf(y);
            float wx1 = x - x0, wy1 = y - y0;
            bool vx0 = (x0        >= 0.f) && (x0        < 64.f);
            bool vx1 = (x0 + 1.f  >= 0.f) && (x0 + 1.f  < 64.f);
            bool vy0 = (y0        >= 0.f) && (y0        < 64.f);
            bool vy1 = (y0 + 1.f  >= 0.f) && (y0 + 1.f  < 64.f);
            float w0 = (vx0 && vy0) ? (1.f - wx1) * (1.f - wy1) : 0.f;
            float w1 = (vx1 && vy0) ? wx1 * (1.f - wy1)         : 0.f;
            float w2 = (vx0 && vy1) ? (1.f - wx1) * wy1         : 0.f;
            float w3 = (vx1 && vy1) ? wx1 * wy1                 : 0.f;
            unsigned u0 = (unsigned)__half_as_ushort(__float2half_rn(w0)) * 0x10001u;
            unsigned u1 = (unsigned)__half_as_ushort(__float2half_rn(w1)) * 0x10001u;
            unsigned u2 = (unsigned)__half_as_ushort(__float2half_rn(w2)) * 0x10001u;
            unsigned u3 = (unsigned)__half_as_ushort(__float2half_rn(w3)) * 0x10001u;
            int cx0 = (int)fminf(fmaxf(x0,       0.f), 63.f);
            int cx1 = (int)fminf(fmaxf(x0 + 1.f, 0.f), 63.f);
            int cy0 = (int)fminf(fmaxf(y0,       0.f), 63.f);
            int cy1 = (int)fminf(fmaxf(y0 + 1.f, 0.f), 63.f);
            unsigned o00 = (unsigned)((cy0*64 + cx0) * 512);
            unsigned oc  = o00 | (unsigned)(cx1 != cx0) | ((unsigned)(cy1 != cy0) << 1);
            s_wgt[pix][s] = make_uint4(u0, u1, u2, u3);
            s_oc [pix][s] = oc;
        }
    }
    __syncwarp();

    __half2 a0, a1, a2, a3;
    if (pixValid) {
        // ---- phase B: 32-iteration loop with corner-register caching ----
        __half2 X0 = __float2half2_rn(-65504.f);
        __half2 X1 = X0, X2 = X0, X3 = X0;
        uint4 v00={0,0,0,0}, v01={0,0,0,0}, v10={0,0,0,0}, v11={0,0,0,0};
        unsigned prev = 0xFFFFFFFFu;
        #pragma unroll 4
        for (int i = 0; i < 32; i++) {
            int s = shalf + i;
            uint4    wp = s_wgt[pix][s];
            unsigned oc = s_oc [pix][s];
            unsigned nl = (oc != prev); prev = oc;
            unsigned o00 = oc & ~3u;
            unsigned dxo = (oc & 1u) << 9;
            unsigned dyo = (oc & 2u) << 14;
            const char* p0 = fbB + o00;
            ld_cond(nl, p0,             v00);
            ld_cond(nl, p0 + dxo,       v01);
            ld_cond(nl, p0 + dyo,       v10);
            ld_cond(nl, p0 + dxo + dyo, v11);
            fma_max(wp, v00, v01, v10, v11, X0, X1, X2, X3);
        }
        a0 = X0; a1 = X1; a2 = X2; a3 = X3;
    } else {
        a0 = __float2half2_rn(0.0f);
        a1 = a0; a2 = a0; a3 = a0;
    }

    // ---- merge the two half-line accumulators per pixel ----
    __syncthreads();                       // all warps done reading s_wgt/s_oc
    uint4* s_acc = (uint4*)&s_wgt[0][0];   // reuse weight buffer (4 pix x 32 lanes)
    if (wy & 1) {
        uint4 pk;
        pk.x = *reinterpret_cast<unsigned*>(&a0);
        pk.y = *reinterpret_cast<unsigned*>(&a1);
        pk.z = *reinterpret_cast<unsigned*>(&a2);
        pk.w = *reinterpret_cast<unsigned*>(&a3);
        s_acc[pix * 32 + lane] = pk;
    }
    __syncthreads();
    if (!(wy & 1)) {
        uint4 pk = s_acc[pix * 32 + lane];
        a0 = __hmax2(a0, *reinterpret_cast<__half2*>(&pk.x));
        a1 = __hmax2(a1, *reinterpret_cast<__half2*>(&pk.y));
        a2 = __hmax2(a2, *reinterpret_cast<__half2*>(&pk.z));
        a3 = __hmax2(a3, *reinterpret_cast<__half2*>(&pk.w));
        float* row = &s_out[pix][0];
        float2 t;
        t = __half22float2(a0); row[lane*8 + 0] = t.x; row[lane*8 + 1] = t.y;
        t = __half22float2(a1); row[lane*8 + 2] = t.x; row[lane*8 + 3] = t.y;
        t = __half22float2(a2); row[lane*8 + 4] = t.x; row[lane*8 + 5] = t.y;
        t = __half22float2(a3); row[lane*8 + 6] = t.x; row[lane*8 + 7] = t.y;
    }
    __syncthreads();

    // ---- coalesced store: thread = channel, 4 pixels -> 1x STG.128 ----
    {
        int c   = wy * 32 + lane;          // 0..255
        int gpb = blockIdx.x * 4;
        int nB  = gpb >> 12;
        int pB  = gpb & 4095;
        float4 o4 = make_float4(s_out[0][c], s_out[1][c], s_out[2][c], s_out[3][c]);
        size_t base = ((size_t)(nB * C_CH + c)) * HWPIX + pB;
        *reinterpret_cast<float4*>(out + base) = o4;
    }
}

// ---------------- launch ------------------------------------------------------
extern "C" void kernel_launch(void* const* d_in, const int* in_sizes, int n_in,
                              void* d_out, int out_size) {
    (void)in_sizes; (void)n_in; (void)out_size;
    const float* feat2 = (const float*)d_in[1];
    const float* P1    = (const float*)d_in[2];
    const float* P2    = (const float*)d_in[3];

    prep_kernel<<<1025, dim3(32, 8)>>>(feat2, P1, P2);
    sample_kernel<<<NPIX / 4, dim3(32, 8)>>>((float*)d_out);
}